// round 7
// baseline (speedup 1.0000x reference)
#include <cuda_runtime.h>

#define B_ 256
#define C_ 2048
#define N_ 288
#define K_ 6
#define CQ_ 512           // columns per C-quarter
#define NT_ 96            // threads per assign CTA (one n-third)
#define AG_ 1332          // assign grid (333 CTAs per quarter)

typedef unsigned long long u64;

// scratch (no allocations allowed)
__device__ unsigned char g_assign[B_ * N_];
__device__ float g_inv[B_ * K_];
// partial dots: [256 b][4 cq][7 (6 dots + xnorm)][288 n]
__device__ float g_part[(size_t)B_ * 4 * 7 * N_];

__device__ __forceinline__ u64 pack2(float lo, float hi) {
    u64 p;
    asm("mov.b64 %0, {%1, %2};" : "=l"(p) : "f"(lo), "f"(hi));
    return p;
}
__device__ __forceinline__ void unpack2(u64 p, float& lo, float& hi) {
    asm("mov.b64 {%0, %1}, %2;" : "=f"(lo), "=f"(hi) : "l"(p));
}
__device__ __forceinline__ float unpack_sum(u64 p) {
    float lo, hi;
    unpack2(p, lo, hi);
    return lo + hi;
}
__device__ __forceinline__ void fma2(u64& d, u64 a, u64 b) {
    asm("fma.rn.f32x2 %0, %1, %2, %3;" : "=l"(d) : "l"(a), "l"(b), "l"(d));
}

// ---------------------------------------------------------------------------
// Kernel A: partial dot products, balanced tiling.
// grid = 1332 CTAs x 96 threads. CTA g owns C-quarter cq = g&3 (cluster slice
// staged once in 12KB shared), then strides over tiles (b, n-third):
// 768 tiles per quarter, stride 333 -> per-SM tile counts ~13-14 (balanced).
// 16-column chunks with next-chunk prefetch -> 16 loads in flight per warp.
// ---------------------------------------------------------------------------
__global__ void __launch_bounds__(NT_, 9) assign_part_kernel(const float* __restrict__ x,
                                                             const float* __restrict__ cl) {
    __shared__ float sCl[K_][CQ_];

    const int g = blockIdx.x;
    const int cq = g & 3;
    const int u = g >> 2;          // 0..332
    const int t = threadIdx.x;     // 0..95

    // stage cluster quarter once (float4, coalesced)
    for (int i = t; i < K_ * (CQ_ / 4); i += NT_) {
        int k = i >> 7;            // / 128
        int cc = i & 127;
        ((float4*)sCl[k])[cc] = ((const float4*)(cl + k * C_ + cq * CQ_))[cc];
    }
    __syncthreads();

    for (int tile = u; tile < 768; tile += 333) {
        const int b = tile / 3;
        const int nt = tile - b * 3;
        const float* xh = x + (size_t)b * ((size_t)C_ * N_)
                            + (size_t)cq * CQ_ * N_ + nt * NT_ + t;

        u64 d2[K_];
        #pragma unroll
        for (int k = 0; k < K_; k++) d2[k] = 0ull;
        u64 xn2 = 0ull;

        float v[16], vn[16];
        #pragma unroll
        for (int uu = 0; uu < 16; uu++) v[uu] = xh[(size_t)uu * N_];

        #pragma unroll 1
        for (int c = 0; c < CQ_; c += 16) {
            if (c + 16 < CQ_) {
                #pragma unroll
                for (int uu = 0; uu < 16; uu++) vn[uu] = xh[(size_t)(c + 16 + uu) * N_];
            }
            u64 vp[8];
            #pragma unroll
            for (int uu = 0; uu < 8; uu++) vp[uu] = pack2(v[2 * uu], v[2 * uu + 1]);
            #pragma unroll
            for (int uu = 0; uu < 8; uu++) fma2(xn2, vp[uu], vp[uu]);
            #pragma unroll
            for (int k = 0; k < K_; k++) {
                ulonglong2 q0 = *(const ulonglong2*)&sCl[k][c];
                ulonglong2 q1 = *(const ulonglong2*)&sCl[k][c + 4];
                ulonglong2 q2 = *(const ulonglong2*)&sCl[k][c + 8];
                ulonglong2 q3 = *(const ulonglong2*)&sCl[k][c + 12];
                fma2(d2[k], vp[0], q0.x);
                fma2(d2[k], vp[1], q0.y);
                fma2(d2[k], vp[2], q1.x);
                fma2(d2[k], vp[3], q1.y);
                fma2(d2[k], vp[4], q2.x);
                fma2(d2[k], vp[5], q2.y);
                fma2(d2[k], vp[6], q3.x);
                fma2(d2[k], vp[7], q3.y);
            }
            #pragma unroll
            for (int uu = 0; uu < 16; uu++) v[uu] = vn[uu];
        }

        float* p = g_part + ((size_t)(b * 4 + cq) * 7) * N_ + nt * NT_ + t;
        #pragma unroll
        for (int k = 0; k < K_; k++) p[k * N_] = unpack_sum(d2[k]);
        p[6 * N_] = unpack_sum(xn2);
    }
}

// ---------------------------------------------------------------------------
// Kernel C: combine 4 partials, argmin, counts. grid = B, 288 threads.
// ---------------------------------------------------------------------------
__global__ void __launch_bounds__(N_) argmin_kernel(const float* __restrict__ cl) {
    __shared__ float sCn[K_];
    __shared__ int   sCnt[K_];

    const int b = blockIdx.x;
    const int t = threadIdx.x;
    const int w = t >> 5;
    const int l = t & 31;

    if (t < K_) sCnt[t] = 0;

    if (w < K_) {
        float s = 0.f;
        for (int c = l; c < C_; c += 32) {
            float v = __ldg(&cl[w * C_ + c]);
            s = fmaf(v, v, s);
        }
        #pragma unroll
        for (int o = 16; o; o >>= 1) s += __shfl_xor_sync(0xffffffffu, s, o);
        if (l == 0) sCn[w] = s;
    }
    __syncthreads();

    const float* pb = g_part + (size_t)b * 4 * 7 * N_ + t;

    float dot[K_];
    #pragma unroll
    for (int k = 0; k < K_; k++) dot[k] = 0.f;
    float xn = 0.f;
    #pragma unroll
    for (int cq = 0; cq < 4; cq++) {
        #pragma unroll
        for (int k = 0; k < K_; k++) dot[k] += pb[(cq * 7 + k) * N_];
        xn += pb[(cq * 7 + 6) * N_];
    }

    int   a  = 0;
    float bd = (xn + sCn[0]) - 2.0f * dot[0];
    #pragma unroll
    for (int k = 1; k < K_; k++) {
        float e = (xn + sCn[k]) - 2.0f * dot[k];
        if (e < bd) { bd = e; a = k; }
    }
    g_assign[b * N_ + t] = (unsigned char)a;

    atomicAdd(&sCnt[a], 1);
    __syncthreads();
    if (t < K_) {
        int cnt = sCnt[t];
        g_inv[b * K_ + t] = (cnt > 0) ? (1.0f / (float)cnt) : 0.0f;
    }
}

// ---------------------------------------------------------------------------
// Kernel B: scatter-mean. grid = 16*B CTAs of 128 threads (4 warps).
// q-major CTA ordering with priority {3,7,11,15, 2,6,10,14, ...}: the first
// waves read the columns still resident in L2 from the assign pass (tail of
// each C-quarter), turning ~17-20% of this kernel's traffic into L2 hits.
// Per warp: one-hot masks packed f32x2, next-row prefetch, split-shuffle
// reduce (lanes<16 own k0..2, lanes>=16 own k3..5).
// ---------------------------------------------------------------------------
__global__ void __launch_bounds__(128, 5) sum_kernel(const float* __restrict__ x,
                                                     float* __restrict__ out) {
    const int qi = blockIdx.x >> 8;          // 0..15 (priority slot)
    const int b  = blockIdx.x & 255;
    const int q  = (qi & 3) * 4 + 3 - (qi >> 2);   // {3,7,11,15,2,6,10,14,...}
    const int w = threadIdx.x >> 5;
    const int l = threadIdx.x & 31;

    // packed one-hot masks for this lane's 9 positions (fixed per batch)
    u64 m2[9][3];
    #pragma unroll
    for (int j = 0; j < 9; j++) {
        int a = (int)g_assign[b * N_ + j * 32 + l];
        #pragma unroll
        for (int p = 0; p < 3; p++)
            m2[j][p] = pack2((a == 2 * p) ? 1.0f : 0.0f,
                             (a == 2 * p + 1) ? 1.0f : 0.0f);
    }

    const bool hi = (l >= 16);
    const int  lk = l & 15;
    const int  myk = lk + (hi ? 3 : 0);
    const float invSel = (lk < 3) ? g_inv[b * K_ + myk] : 0.0f;

    const float* xb = x + (size_t)b * ((size_t)C_ * N_);
    const int c0 = q * 128 + w * 32;

    float v[9], vn[9];
    {
        const float* row = xb + (size_t)c0 * N_;
        #pragma unroll
        for (int j = 0; j < 9; j++) v[j] = row[j * 32 + l];
    }

    #pragma unroll 1
    for (int i = 0; i < 32; i++) {
        const int c = c0 + i;
        if (i + 1 < 32) {
            const float* rn = xb + (size_t)(c + 1) * N_;
            #pragma unroll
            for (int j = 0; j < 9; j++) vn[j] = rn[j * 32 + l];
        }

        u64 s2[3];
        #pragma unroll
        for (int p = 0; p < 3; p++) s2[p] = 0ull;
        #pragma unroll
        for (int j = 0; j < 9; j++) {
            u64 vv = pack2(v[j], v[j]);
            #pragma unroll
            for (int p = 0; p < 3; p++) fma2(s2[p], m2[j][p], vv);
        }

        float s[K_];
        unpack2(s2[0], s[0], s[1]);
        unpack2(s2[1], s[2], s[3]);
        unpack2(s2[2], s[4], s[5]);

        float r0 = hi ? s[3] : s[0];
        float r1 = hi ? s[4] : s[1];
        float r2 = hi ? s[5] : s[2];
        float o0 = hi ? s[0] : s[3];
        float o1 = hi ? s[1] : s[4];
        float o2 = hi ? s[2] : s[5];
        r0 += __shfl_xor_sync(0xffffffffu, o0, 16);
        r1 += __shfl_xor_sync(0xffffffffu, o1, 16);
        r2 += __shfl_xor_sync(0xffffffffu, o2, 16);
        #pragma unroll
        for (int o = 8; o; o >>= 1) {
            r0 += __shfl_xor_sync(0xffffffffu, r0, o);
            r1 += __shfl_xor_sync(0xffffffffu, r1, o);
            r2 += __shfl_xor_sync(0xffffffffu, r2, o);
        }

        float res = r0;
        res = (lk == 1) ? r1 : res;
        res = (lk == 2) ? r2 : res;
        if (lk < 3) out[((size_t)b * C_ + c) * K_ + myk] = res * invSel;

        #pragma unroll
        for (int j = 0; j < 9; j++) v[j] = vn[j];
    }
}

extern "C" void kernel_launch(void* const* d_in, const int* in_sizes, int n_in,
                              void* d_out, int out_size) {
    const float* x  = (const float*)d_in[0];   // [256, 2048, 24, 12]
    const float* cl = (const float*)d_in[1];   // [6, 2048]
    float* out = (float*)d_out;                // [B, C, K]

    assign_part_kernel<<<AG_, NT_>>>(x, cl);
    argmin_kernel<<<B_, N_>>>(cl);
    sum_kernel<<<B_ * 16, 128>>>(x, out);
}